// round 17
// baseline (speedup 1.0000x reference)
#include <cuda_runtime.h>
#include <cuda_fp16.h>
#include <math.h>
#include <stdint.h>

#define HIDDEN 2048
#define NH 16
#define NKV 4
#define HD 128
#define KVD 512
#define BATCH 2
#define SEQ 2048
#define MTOT (BATCH*SEQ)   // 4096
#define QKOUT 2560         // merged Q|K projection output width

// ---------------- scratch (static device globals; no allocs allowed) -------
// fp16 (hi, sum) operands: hi = fp16(x); sum = fp16(hi + 64*(x - hi))
__device__ __half g_hsh [(size_t)MTOT * HIDDEN];
__device__ __half g_hss [(size_t)MTOT * HIDDEN];
__device__ __half g_wqkh[(size_t)QKOUT * HIDDEN];
__device__ __half g_wqks[(size_t)QKOUT * HIDDEN];
__device__ __half g_wvh [(size_t)KVD * HIDDEN];       // plain fp16 (V-proj)
__device__ __half g_woh [(size_t)HIDDEN * HIDDEN];    // plain fp16 (O-proj)
__device__ __half g_aoh [(size_t)MTOT * HIDDEN];      // plain fp16 (O-proj in)

// attention fp16 operands (all plain)
__device__ __half g_qh [(size_t)MTOT * HIDDEN];
__device__ __half g_kh [(size_t)MTOT * KVD];
__device__ __half g_vth[(size_t)BATCH * NKV * HD * SEQ];

// RoPE cos/sin table: [pos][i] -> (cos, sin)
__device__ float2 g_cstab[(size_t)SEQ * 64];

#define SPLIT_S 64.0f
#define SPLIT_SINV (1.0f / 64.0f)

// ---------------- helpers ---------------------------------------------------
__device__ __forceinline__ uint32_t smem_u32(const void* p) {
    return (uint32_t)__cvta_generic_to_shared(p);
}
__device__ __forceinline__ void cpa16(uint32_t smaddr, const void* g) {
    asm volatile("cp.async.cg.shared.global [%0], [%1], 16;" :: "r"(smaddr), "l"(g));
}
__device__ __forceinline__ void cpa_commit() { asm volatile("cp.async.commit_group;"); }
__device__ __forceinline__ void cpa_wait1()  { asm volatile("cp.async.wait_group 1;"); }
__device__ __forceinline__ void cpa_wait0()  { asm volatile("cp.async.wait_group 0;"); }

__device__ __forceinline__ void ldsm_x4(uint32_t* r, uint32_t addr) {
    asm volatile("ldmatrix.sync.aligned.m8n8.x4.shared.b16 {%0,%1,%2,%3}, [%4];"
                 : "=r"(r[0]), "=r"(r[1]), "=r"(r[2]), "=r"(r[3]) : "r"(addr));
}
__device__ __forceinline__ void mma_f16(float* d, const uint32_t* a, const uint32_t* b) {
    asm volatile(
        "mma.sync.aligned.m16n8k16.row.col.f32.f16.f16.f32 "
        "{%0,%1,%2,%3}, {%4,%5,%6,%7}, {%8,%9}, {%0,%1,%2,%3};"
        : "+f"(d[0]), "+f"(d[1]), "+f"(d[2]), "+f"(d[3])
        : "r"(a[0]), "r"(a[1]), "r"(a[2]), "r"(a[3]), "r"(b[0]), "r"(b[1]));
}
__device__ __forceinline__ uint32_t packh2(float x, float y) {
    __half2 v = __floats2half2_rn(x, y);
    return *reinterpret_cast<uint32_t*>(&v);
}
__device__ __forceinline__ void split1(float x, __half& h, __half& s) {
    h = __float2half(x);
    float hf = __half2float(h);
    s = __float2half(fmaf(SPLIT_S, x - hf, hf));
}

// ---------------- RoPE cos/sin table ----------------------------------------
__global__ __launch_bounds__(256) void rope_tab(float2* __restrict__ tab)
{
    int idx = blockIdx.x * 256 + threadIdx.x;     // SEQ*64 total
    int pos = idx >> 6, i = idx & 63;
    float inv = powf(10000.0f, -(float)i / 64.0f);
    float s, c;
    sincosf((float)pos * inv, &s, &c);
    tab[idx] = make_float2(c, s);
}

// ---------------- fused split kernel: all inputs in one launch --------------
__global__ __launch_bounds__(256) void split_all(
    const float* __restrict__ hs, const float* __restrict__ wq,
    const float* __restrict__ wk, const float* __restrict__ wv,
    const float* __restrict__ wo,
    __half* __restrict__ hsh, __half* __restrict__ hss,
    __half* __restrict__ wqkh, __half* __restrict__ wqks,
    __half* __restrict__ wvh, __half* __restrict__ woh)
{
    const int N_HS = MTOT * HIDDEN / 4;
    const int N_WQ = HIDDEN * HIDDEN / 4;
    const int N_WK = KVD * HIDDEN / 4;
    const int B1 = N_HS, B2 = B1 + N_WQ, B3 = B2 + N_WK, B4 = B3 + N_WK;
    const int total = B4 + N_WQ;

    for (int i = blockIdx.x * blockDim.x + threadIdx.x; i < total; i += gridDim.x * blockDim.x) {
        const float* src;
        __half *dh, *ds;
        int j;
        if (i < B1)      { j = i;      src = hs; dh = hsh;  ds = hss; }
        else if (i < B2) { j = i - B1; src = wq; dh = wqkh; ds = wqks; }
        else if (i < B3) { j = i - B2; src = wk; dh = wqkh + (size_t)HIDDEN * HIDDEN;
                                                 ds = wqks + (size_t)HIDDEN * HIDDEN; }
        else if (i < B4) { j = i - B3; src = wv; dh = wvh;  ds = 0; }
        else             { j = i - B4; src = wo; dh = woh;  ds = 0; }

        float4 x = ((const float4*)src)[j];
        __half h0, h1, h2, h3, s0, s1, s2, s3;
        split1(x.x, h0, s0); split1(x.y, h1, s1);
        split1(x.z, h2, s2); split1(x.w, h3, s3);
        ((ushort4*)dh)[j] = make_ushort4(__half_as_ushort(h0), __half_as_ushort(h1),
                                         __half_as_ushort(h2), __half_as_ushort(h3));
        if (ds)
            ((ushort4*)ds)[j] = make_ushort4(__half_as_ushort(s0), __half_as_ushort(s1),
                                             __half_as_ushort(s2), __half_as_ushort(s3));
    }
}

// ============================================================================
// QK projection GEMM (2-MMA corrected) with FUSED RoPE epilogue
// writes plain fp16 qh / kh directly (no fp32 intermediate)
// ============================================================================
#define LDH 40
#define LDB (LDH * 2)
#define ARR (128 * LDB)
#define BUFB (4 * ARR)
#define GSM (2 * BUFB)          // 81920
#define LDT 129                 // fp32 staging tile pitch (floats)

__global__ __launch_bounds__(512) void gemm_qk_rope(
    const __half* __restrict__ Ah_, const __half* __restrict__ As_,
    const __half* __restrict__ Bh_, const __half* __restrict__ Bs_,
    const float2* __restrict__ cstab,
    __half* __restrict__ qh, __half* __restrict__ kh)
{
    extern __shared__ char dsm[];
    const uint32_t base = smem_u32(dsm);

    const int tid  = threadIdx.x;
    const int warp = tid >> 5, lane = tid & 31;
    const int wr = warp & 3, wc = warp >> 2;
    const int row0 = blockIdx.y * 128;
    const int col0 = blockIdx.x * 128;

    const char* src[4] = {
        (const char*)(Ah_ + (size_t)row0 * HIDDEN),
        (const char*)(As_ + (size_t)row0 * HIDDEN),
        (const char*)(Bh_ + (size_t)col0 * HIDDEN),
        (const char*)(Bs_ + (size_t)col0 * HIDDEN)
    };

    const int nChunk = HIDDEN / 32;

    const int lr = tid >> 2;
    const int lc = tid & 3;
    auto loadTile = [&](int t, int buf) {
        #pragma unroll
        for (int a = 0; a < 4; a++) {
            cpa16(base + buf * BUFB + a * ARR + lr * LDB + lc * 16,
                  src[a] + ((size_t)lr * HIDDEN + t * 32) * 2 + lc * 16);
        }
        cpa_commit();
    };

    float acch[2][4][4], accs[2][4][4];
    #pragma unroll
    for (int mi = 0; mi < 2; mi++)
        #pragma unroll
        for (int ni = 0; ni < 4; ni++)
            #pragma unroll
            for (int r = 0; r < 4; r++) { acch[mi][ni][r] = 0.f; accs[mi][ni][r] = 0.f; }

    const uint32_t aoffA = (uint32_t)((wr * 32 + (lane & 15)) * LDB + ((lane >> 4) << 3) * 2);
    const uint32_t aoffB = (uint32_t)((wc * 32 + ((lane >> 4) << 3) + (lane & 7)) * LDB
                                      + (((lane >> 3) & 1) << 3) * 2);

    loadTile(0, 0);

    for (int t = 0; t < nChunk; t++) {
        const int buf = t & 1;
        if (t + 1 < nChunk) { loadTile(t + 1, buf ^ 1); cpa_wait1(); }
        else                { cpa_wait0(); }
        __syncthreads();

        const uint32_t bo = base + buf * BUFB;

        #pragma unroll
        for (int ks = 0; ks < 2; ks++) {
            const uint32_t kb = (uint32_t)(ks * 32);

            uint32_t ah[2][4], as_[2][4];
            ldsm_x4(ah[0],  bo + 0 * ARR + aoffA + kb);
            ldsm_x4(ah[1],  bo + 0 * ARR + aoffA + kb + 16 * LDB);
            ldsm_x4(as_[0], bo + 1 * ARR + aoffA + kb);
            ldsm_x4(as_[1], bo + 1 * ARR + aoffA + kb + 16 * LDB);

            uint32_t bh[4][2], bs[4][2], tmp[4];
            ldsm_x4(tmp, bo + 2 * ARR + aoffB + kb);
            bh[0][0] = tmp[0]; bh[0][1] = tmp[1]; bh[1][0] = tmp[2]; bh[1][1] = tmp[3];
            ldsm_x4(tmp, bo + 2 * ARR + aoffB + kb + 16 * LDB);
            bh[2][0] = tmp[0]; bh[2][1] = tmp[1]; bh[3][0] = tmp[2]; bh[3][1] = tmp[3];
            ldsm_x4(tmp, bo + 3 * ARR + aoffB + kb);
            bs[0][0] = tmp[0]; bs[0][1] = tmp[1]; bs[1][0] = tmp[2]; bs[1][1] = tmp[3];
            ldsm_x4(tmp, bo + 3 * ARR + aoffB + kb + 16 * LDB);
            bs[2][0] = tmp[0]; bs[2][1] = tmp[1]; bs[3][0] = tmp[2]; bs[3][1] = tmp[3];

            #pragma unroll
            for (int mi = 0; mi < 2; mi++)
                #pragma unroll
                for (int ni = 0; ni < 4; ni++) {
                    mma_f16(acch[mi][ni], ah[mi],  bh[ni]);
                    mma_f16(accs[mi][ni], as_[mi], bs[ni]);
                }
        }
        __syncthreads();
    }

    // stage folded fp32 tile into smem (operand buffers are free now)
    float* T = (float*)dsm;
    #pragma unroll
    for (int mi = 0; mi < 2; mi++)
        #pragma unroll
        for (int ni = 0; ni < 4; ni++) {
            const int rl = wr * 32 + mi * 16 + (lane >> 2);
            const int cl = wc * 32 + ni * 8 + 2 * (lane & 3);
            T[rl * LDT + cl]           = acch[mi][ni][0] + (accs[mi][ni][0] - acch[mi][ni][0]) * SPLIT_SINV;
            T[rl * LDT + cl + 1]       = acch[mi][ni][1] + (accs[mi][ni][1] - acch[mi][ni][1]) * SPLIT_SINV;
            T[(rl + 8) * LDT + cl]     = acch[mi][ni][2] + (accs[mi][ni][2] - acch[mi][ni][2]) * SPLIT_SINV;
            T[(rl + 8) * LDT + cl + 1] = acch[mi][ni][3] + (accs[mi][ni][3] - acch[mi][ni][3]) * SPLIT_SINV;
        }
    __syncthreads();

    // fused RoPE: 128 rows x 64 pairs; pair (i, i+64) within this head tile
    #pragma unroll
    for (int k = 0; k < 16; k++) {
        const int pid = tid + k * 512;
        const int r = pid >> 6, i = pid & 63;
        const int row = row0 + r;
        const int pos = row & (SEQ - 1);
        const float a  = T[r * LDT + i];
        const float b2 = T[r * LDT + i + 64];
        const float2 cs = cstab[pos * 64 + i];
        const float r0 = a * cs.x - b2 * cs.y;
        const float r1 = b2 * cs.x + a * cs.y;
        if (col0 < HIDDEN) {
            const int h = col0 >> 7;
            const size_t o = (size_t)row * HIDDEN + (h << 7) + i;
            qh[o]      = __float2half(r0);
            qh[o + 64] = __float2half(r1);
        } else {
            const int kvh = (col0 - HIDDEN) >> 7;
            const size_t o = (size_t)row * KVD + (kvh << 7) + i;
            kh[o]      = __float2half(r0);
            kh[o + 64] = __float2half(r1);
        }
    }
}

// ============================================================================
// Plain fp16 GEMM — O-projection (fp32 out) and V-projection (fused transpose)
// ============================================================================
#define PLDB 144                 // 64 halfs + 16B pad
#define PARR (128 * PLDB)        // 18432
#define PBUF (2 * PARR)          // 36864
#define PGSM (2 * PBUF)          // 73728

template<bool VTRANS>
__global__ __launch_bounds__(512) void gemm_plain_t(
    const __half* __restrict__ Ah_, const __half* __restrict__ Bh_,
    float* __restrict__ C, __half* __restrict__ vth, int N)
{
    extern __shared__ char dsm[];
    const uint32_t base = smem_u32(dsm);

    const int tid  = threadIdx.x;
    const int warp = tid >> 5, lane = tid & 31;
    const int wr = warp & 3, wc = warp >> 2;
    const int row0 = blockIdx.y * 128;
    const int col0 = blockIdx.x * 128;

    const char* srcA = (const char*)(Ah_ + (size_t)row0 * HIDDEN);
    const char* srcB = (const char*)(Bh_ + (size_t)col0 * HIDDEN);

    const int nChunk = HIDDEN / 64;    // 32

    auto loadTile = [&](int t, int buf) {
        #pragma unroll
        for (int i = 0; i < 2; i++) {
            int idx = tid + i * 512;        // 0..1023
            int r = idx >> 3, c = idx & 7;
            size_t go = ((size_t)r * HIDDEN + t * 64) * 2 + c * 16;
            cpa16(base + buf * PBUF + 0 * PARR + r * PLDB + c * 16, srcA + go);
            cpa16(base + buf * PBUF + 1 * PARR + r * PLDB + c * 16, srcB + go);
        }
        cpa_commit();
    };

    float acc[2][4][4];
    #pragma unroll
    for (int mi = 0; mi < 2; mi++)
        #pragma unroll
        for (int ni = 0; ni < 4; ni++)
            #pragma unroll
            for (int r = 0; r < 4; r++) acc[mi][ni][r] = 0.f;

    const uint32_t aoffA = (uint32_t)((wr * 32 + (lane & 15)) * PLDB + ((lane >> 4) << 4));
    const uint32_t aoffB = (uint32_t)((wc * 32 + ((lane >> 4) << 3) + (lane & 7)) * PLDB
                                      + (((lane >> 3) & 1) << 4));

    loadTile(0, 0);

    for (int t = 0; t < nChunk; t++) {
        const int buf = t & 1;
        if (t + 1 < nChunk) { loadTile(t + 1, buf ^ 1); cpa_wait1(); }
        else                { cpa_wait0(); }
        __syncthreads();

        const uint32_t bo = base + buf * PBUF;

        #pragma unroll
        for (int ks = 0; ks < 4; ks++) {
            const uint32_t kb = (uint32_t)(ks * 32);

            uint32_t ah[2][4];
            ldsm_x4(ah[0], bo + 0 * PARR + aoffA + kb);
            ldsm_x4(ah[1], bo + 0 * PARR + aoffA + kb + 16 * PLDB);

            uint32_t bh[4][2], tmp[4];
            ldsm_x4(tmp, bo + 1 * PARR + aoffB + kb);
            bh[0][0] = tmp[0]; bh[0][1] = tmp[1]; bh[1][0] = tmp[2]; bh[1][1] = tmp[3];
            ldsm_x4(tmp, bo + 1 * PARR + aoffB + kb + 16 * PLDB);
            bh[2][0] = tmp[0]; bh[2][1] = tmp[1]; bh[3][0] = tmp[2]; bh[3][1] = tmp[3];

            #pragma unroll
            for (int mi = 0; mi < 2; mi++)
                #pragma unroll
                for (int ni = 0; ni < 4; ni++)
                    mma_f16(acc[mi][ni], ah[mi], bh[ni]);
        }
        __syncthreads();
    }

    if (!VTRANS) {
        #pragma unroll
        for (int mi = 0; mi < 2; mi++)
            #pragma unroll
            for (int ni = 0; ni < 4; ni++) {
                const int row = row0 + wr * 32 + mi * 16 + (lane >> 2);
                const int col = col0 + wc * 32 + ni * 8 + 2 * (lane & 3);
                *(float2*)(C + (size_t)row * N + col)       = make_float2(acc[mi][ni][0], acc[mi][ni][1]);
                *(float2*)(C + (size_t)(row + 8) * N + col) = make_float2(acc[mi][ni][2], acc[mi][ni][3]);
            }
    } else {
        // stage fp32 tile, then transposed fp16 write: vth[bh*HD+d][s]
        float* T = (float*)dsm;
        #pragma unroll
        for (int mi = 0; mi < 2; mi++)
            #pragma unroll
            for (int ni = 0; ni < 4; ni++) {
                const int rl = wr * 32 + mi * 16 + (lane >> 2);
                const int cl = wc * 32 + ni * 8 + 2 * (lane & 3);
                T[rl * LDT + cl]           = acc[mi][ni][0];
                T[rl * LDT + cl + 1]       = acc[mi][ni][1];
                T[(rl + 8) * LDT + cl]     = acc[mi][ni][2];
                T[(rl + 8) * LDT + cl + 1] = acc[mi][ni][3];
            }
        __syncthreads();

        const int b = row0 / SEQ;
        const int kvh = col0 >> 7;
        const int bh = b * NKV + kvh;
        const int s0 = row0 & (SEQ - 1);
        #pragma unroll
        for (int k = 0; k < 32; k++) {
            const int eid = tid + k * 512;
            const int d = eid >> 7, sl = eid & 127;
            vth[(size_t)(bh * HD + d) * SEQ + s0 + sl] = __float2half(T[sl * LDT + d]);
        }
    }
}

// ============================================================================
// Persistent MMA flash attention (causal, GQA) — all plain fp16 operands
// ============================================================================
#define ATT_BQ 128
#define ATT_BKV 64
#define ATT_GRID 148
#define N_ITEMS 512             // 16 qb x 16 h x 2 b
#define SQ_LDB 272              // 128 halfs + 16B pad
#define SV_LDB 144              // 64 halfs + 16B pad
#define KTILE_B 17408           // 64 * SQ_LDB
#define VTILE_B 18432           // 128 * SV_LDB
#define OFF_QH 0
#define OFF_K  34816            // + buf*KTILE_B
#define OFF_VT 69632            // + buf*VTILE_B
#define OFF_MSK 106496
#define ATT_SM 114688

__global__ __launch_bounds__(256) void attn_mma(
    const __half* __restrict__ qh, const __half* __restrict__ kh,
    const __half* __restrict__ vth,
    const int* __restrict__ amask,
    __half* __restrict__ aoh)
{
    extern __shared__ char sm[];
    const uint32_t base = smem_u32(sm);
    const int cta = blockIdx.x;
    const int tid = threadIdx.x, warp = tid >> 5, lane = tid & 31;
    const float scale = 0.08838834764831845f;

    const uint32_t aoffQ = (uint32_t)((warp * 16 + (lane & 15)) * SQ_LDB + ((lane >> 4) << 4));
    const uint32_t boffK = (uint32_t)(((lane >> 4) * 8 + (lane & 7)) * SQ_LDB + (((lane >> 3) & 1) << 4));
    const uint32_t boffV = (uint32_t)(((lane >> 4) * 8 + (lane & 7)) * SV_LDB + (((lane >> 3) & 1) << 4));
    const int* msk = (const int*)(sm + OFF_MSK);

    for (int p = 0; p < (N_ITEMS + ATT_GRID - 1) / ATT_GRID; p++) {
        const int w = p * ATT_GRID + ((p & 1) ? (ATT_GRID - 1 - cta) : cta);
        if (w >= N_ITEMS) continue;
        const int qb = 15 - (w >> 5);          // descending-qb order
        const int rem = w & 31;
        const int h = rem >> 1;
        const int b = rem & 1;
        const int kvh = h / (NH / NKV);
        const int bh = b * NKV + kvh;

        __syncthreads();   // previous item's smem consumers done

        // load Q tile
        {
            const size_t qrow0 = (size_t)(b * SEQ + qb * ATT_BQ);
            #pragma unroll
            for (int i = 0; i < 8; i++) {
                int id = tid + i * 256;
                int r = id >> 4, c = id & 15;
                cpa16(base + OFF_QH + r * SQ_LDB + c * 16,
                      qh + (qrow0 + r) * HIDDEN + (size_t)h * HD + c * 8);
            }
            cpa_commit();
        }
        const int mlen = (qb + 1) * ATT_BQ;
        for (int i = tid; i < mlen; i += 256)
            ((int*)(sm + OFF_MSK))[i] = amask[b * SEQ + i];

        const int nTiles = (qb + 1) * (ATT_BQ / ATT_BKV);   // (qb+1)*2

        auto loadKV = [&](int t, int buf) {
            const int kv0 = t * ATT_BKV;
            #pragma unroll
            for (int i = 0; i < 4; i++) {       // K: 64 rows x 16 chunks
                int id = tid + i * 256;
                int r = id >> 4, c = id & 15;
                cpa16(base + OFF_K + buf * KTILE_B + r * SQ_LDB + c * 16,
                      kh + (size_t)(b * SEQ + kv0 + r) * KVD + (size_t)kvh * HD + c * 8);
            }
            #pragma unroll
            for (int i = 0; i < 4; i++) {       // V: 128 rows x 8 chunks
                int id = tid + i * 256;
                int r = id >> 3, c = id & 7;
                cpa16(base + OFF_VT + buf * VTILE_B + r * SV_LDB + c * 16,
                      vth + (size_t)(bh * HD + r) * SEQ + kv0 + c * 8);
            }
            cpa_commit();
        };

        float O[16][4];
        #pragma unroll
        for (int i = 0; i < 16; i++)
            #pragma unroll
            for (int r = 0; r < 4; r++) O[i][r] = 0.f;
        float m0 = -1e30f, m1 = -1e30f, l0 = 0.f, l1 = 0.f;

        loadKV(0, 0);
        cpa_wait0();
        __syncthreads();

        const int rowg0 = qb * ATT_BQ + warp * 16 + (lane >> 2);
        const int rowg1 = rowg0 + 8;

        for (int t = 0; t < nTiles; t++) {
            const int buf = t & 1;
            const int kv0 = t * ATT_BKV;

            __syncthreads();
            if (t + 1 < nTiles) { loadKV(t + 1, buf ^ 1); cpa_wait1(); }
            else                { cpa_wait0(); }
            __syncthreads();

            const uint32_t kb_h = base + OFF_K + buf * KTILE_B;

            // ---- S = Q K^T (plain fp16) ----
            float sf[8][4];
            #pragma unroll
            for (int nt = 0; nt < 8; nt++)
                #pragma unroll
                for (int r = 0; r < 4; r++) sf[nt][r] = 0.f;

            #pragma unroll
            for (int ksI = 0; ksI < 8; ksI++) {
                uint32_t ah[4];
                ldsm_x4(ah, base + OFF_QH + aoffQ + ksI * 32);
                #pragma unroll
                for (int ntp = 0; ntp < 4; ntp++) {
                    uint32_t tmp[4];
                    ldsm_x4(tmp, kb_h + boffK + (uint32_t)(ntp * 16 * SQ_LDB) + ksI * 32);
                    uint32_t b0[2] = {tmp[0], tmp[1]}, b1[2] = {tmp[2], tmp[3]};
                    mma_f16(sf[ntp * 2],     ah, b0);
                    mma_f16(sf[ntp * 2 + 1], ah, b1);
                }
            }

            // scale + mask
            #pragma unroll
            for (int nt = 0; nt < 8; nt++)
                #pragma unroll
                for (int r = 0; r < 4; r++) {
                    float s = sf[nt][r] * scale;
                    int col = kv0 + nt * 8 + 2 * (lane & 3) + (r & 1);
                    int row = (r < 2) ? rowg0 : rowg1;
                    if (col > row || msk[col] == 0) s = -1e30f;
                    sf[nt][r] = s;
                }

            // online softmax over 64 columns
            float mx0 = m0, mx1 = m1;
            #pragma unroll
            for (int nt = 0; nt < 8; nt++) {
                mx0 = fmaxf(mx0, fmaxf(sf[nt][0], sf[nt][1]));
                mx1 = fmaxf(mx1, fmaxf(sf[nt][2], sf[nt][3]));
            }
            mx0 = fmaxf(mx0, __shfl_xor_sync(0xffffffffu, mx0, 1));
            mx0 = fmaxf(mx0, __shfl_xor_sync(0xffffffffu, mx0, 2));
            mx1 = fmaxf(mx1, __shfl_xor_sync(0xffffffffu, mx1, 1));
            mx1 = fmaxf(mx1, __shfl_xor_sync(0xffffffffu, mx1, 2));

            float sum0 = 0.f, sum1 = 0.f;
            #pragma unroll
            for (int nt = 0; nt < 8; nt++) {
                sf[nt][0] = __expf(sf[nt][0] - mx0);
                sf[nt][1] = __expf(sf[nt][1] - mx0);
                sf[nt][2] = __expf(sf[nt][2] - mx1);
                sf[nt][3] = __expf(sf[nt][3] - mx1);
                sum0 += sf[nt][0] + sf[nt][1];
                sum1 += sf[nt][2] + sf[nt][3];
            }
            sum0 += __shfl_xor_sync(0xffffffffu, sum0, 1);
            sum0 += __shfl_xor_sync(0xffffffffu, sum0, 2);
            sum1 += __shfl_xor_sync(0xffffffffu, sum1, 1);
            sum1 += __shfl_xor_sync(0xffffffffu, sum1, 2);

            float a0 = __expf(m0 - mx0), a1 = __expf(m1 - mx1);
            l0 = l0 * a0 + sum0;
            l1 = l1 * a1 + sum1;
            m0 = mx0; m1 = mx1;

            #pragma unroll
            for (int i = 0; i < 16; i++) {
                O[i][0] *= a0; O[i][1] *= a0;
                O[i][2] *= a1; O[i][3] *= a1;
            }

            // P fragments (plain fp16): 4 k16 groups over 64 columns
            uint32_t pH[4][4];
            #pragma unroll
            for (int g = 0; g < 4; g++) {
                int t0 = g * 2, t1 = t0 + 1;
                pH[g][0] = packh2(sf[t0][0], sf[t0][1]);
                pH[g][1] = packh2(sf[t0][2], sf[t0][3]);
                pH[g][2] = packh2(sf[t1][0], sf[t1][1]);
                pH[g][3] = packh2(sf[t1][2], sf[t1][3]);
            }

            // ---- O += P V (plain fp16, direct accumulate) ----
            const uint32_t vb = base + OFF_VT + buf * VTILE_B;
            #pragma unroll
            for (int ntp = 0; ntp < 8; ntp++) {
                #pragma unroll
                for (int g = 0; g < 4; g++) {
                    uint32_t tmp[4];
                    ldsm_x4(tmp, vb + boffV + ntp * 16 * SV_LDB + g * 32);
                    uint32_t b0[2] = {tmp[0], tmp[1]}, b1[2] = {tmp[2], tmp[3]};
                    mma_f16(O[ntp * 2],     pH[g], b0);
                    mma_f16(O[ntp * 2 + 1], pH[g], b1);
                }
            }
        }

        // epilogue: normalize + plain fp16 output
        const float il0 = 1.f / l0, il1 = 1.f / l1;
        #pragma unroll
        for (int nt = 0; nt < 16; nt++) {
            int col = h * HD + nt * 8 + 2 * (lane & 3);
            size_t o0 = (size_t)(b * SEQ + rowg0) * HIDDEN + col;
            size_t o1 = (size_t)(b * SEQ + rowg1) * HIDDEN + col;
            *(uint32_t*)(aoh + o0) = packh2(O[nt][0] * il0, O[nt][1] * il0);
            *(uint32_t*)(aoh + o1) = packh2(O[nt][2] * il1, O[nt][3] * il1);
        }
    }
}

// ---------------- launch ----------------------------------------------------
extern "C" void kernel_launch(void* const* d_in, const int* in_sizes, int n_in,
                              void* d_out, int out_size)
{
    const float* hs    = (const float*)d_in[0];
    const int*   amask = (const int*)  d_in[1];
    const float* wq    = (const float*)d_in[2];
    const float* wk    = (const float*)d_in[3];
    const float* wv    = (const float*)d_in[4];
    const float* wo    = (const float*)d_in[5];
    float* out = (float*)d_out;

    __half *hsh, *hss, *wqkh, *wqks, *wvh, *woh, *aoh;
    cudaGetSymbolAddress((void**)&hsh,  g_hsh);  cudaGetSymbolAddress((void**)&hss,  g_hss);
    cudaGetSymbolAddress((void**)&wqkh, g_wqkh); cudaGetSymbolAddress((void**)&wqks, g_wqks);
    cudaGetSymbolAddress((void**)&wvh,  g_wvh);
    cudaGetSymbolAddress((void**)&woh,  g_woh);
    cudaGetSymbolAddress((void**)&aoh,  g_aoh);

    __half *qh, *kh, *vth;
    cudaGetSymbolAddress((void**)&qh,  g_qh);
    cudaGetSymbolAddress((void**)&kh,  g_kh);
    cudaGetSymbolAddress((void**)&vth, g_vth);

    float2* cstab;
    cudaGetSymbolAddress((void**)&cstab, g_cstab);

    cudaFuncSetAttribute(gemm_qk_rope,        cudaFuncAttributeMaxDynamicSharedMemorySize, GSM);
    cudaFuncSetAttribute(gemm_plain_t<false>, cudaFuncAttributeMaxDynamicSharedMemorySize, PGSM);
    cudaFuncSetAttribute(gemm_plain_t<true>,  cudaFuncAttributeMaxDynamicSharedMemorySize, PGSM);
    cudaFuncSetAttribute(attn_mma,            cudaFuncAttributeMaxDynamicSharedMemorySize, ATT_SM);

    // RoPE table + fused splits
    rope_tab<<<SEQ * 64 / 256, 256>>>(cstab);
    split_all<<<2048, 256>>>(hs, wq, wk, wv, wo, hsh, hss, wqkh, wqks, wvh, woh);

    // QK projection (2-MMA corrected) with fused RoPE -> qh/kh fp16
    gemm_qk_rope<<<dim3(QKOUT / 128, MTOT / 128), 512, GSM>>>(
        hsh, hss, wqkh, wqks, cstab, qh, kh);

    // V projection (plain fp16) with fused transpose -> vth fp16
    gemm_plain_t<true><<<dim3(KVD / 128, MTOT / 128), 512, PGSM>>>(
        hsh, wvh, nullptr, vth, KVD);

    // persistent MMA flash attention (all plain fp16; writes plain fp16)
    attn_mma<<<ATT_GRID, 256, ATT_SM>>>(qh, kh, vth, amask, aoh);

    // O-projection: plain fp16 single-MMA (final stage, fp32 out)
    gemm_plain_t<false><<<dim3(HIDDEN / 128, MTOT / 128), 512, PGSM>>>(
        aoh, woh, out, nullptr, HIDDEN);
}